// round 5
// baseline (speedup 1.0000x reference)
#include <cuda_runtime.h>

#define NN 100000
#define GG 2048
#define CAP 64

// ---------------- device scratch (no allocations allowed) ----------------
__device__ int   g_ctr[NN];                 // per-dst edge counter (== degree after build)
__device__ int   g_csr[(size_t)NN * CAP];   // src ids per dst row (fixed stride)
__device__ float g_h  [(size_t)NN * 32];    // current layer h = xW
__device__ float g_out[(size_t)NN * 32];    // layer output / next layer input
__device__ float g_es [NN];
__device__ float g_ed [NN];

// ---------------- CSR build ----------------
__global__ void k_init()
{
    int i = blockIdx.x * blockDim.x + threadIdx.x;
    if (i < NN) {
        g_ctr[i] = 1;                // self loop occupies slot 0
        g_csr[(size_t)i * CAP] = i;
    }
}

__global__ void k_scatter(const int* __restrict__ src,
                          const int* __restrict__ dst, int E)
{
    int e = blockIdx.x * blockDim.x + threadIdx.x;
    if (e < E) {
        int d = dst[e];
        int s = src[e];
        if ((unsigned)d < NN && (unsigned)s < NN) {
            int pos = atomicAdd(&g_ctr[d], 1);
            if (pos < CAP) g_csr[(size_t)d * CAP + pos] = s;
        }
    }
}

// ---------------- GEMM: g_h[N,32] = X[N,K] @ W[K,32], fused es/ed ----------------
// block = 256 threads covers 256 nodes. Thread = 8 nodes x 4 out-cols.
// USE_GOUT selects layer input: false -> param X, true -> g_out (previous layer).
template <int K, bool USE_GOUT>
__global__ void k_gemm(const float* __restrict__ X, const float* __restrict__ W,
                       const float* __restrict__ a_s, const float* __restrict__ a_d)
{
    __shared__ float xs[32][260];   // transposed x chunk: xs[kk][node_local]
    __shared__ float ws[32][32];    // W chunk

    const float* __restrict__ src = USE_GOUT ? (const float*)g_out : X;

    int tid  = threadIdx.x;
    int lane = tid & 31;
    int warp = tid >> 5;
    int k4   = lane & 7;
    int ngl  = lane >> 3;
    int nodeBlock = blockIdx.x * 256;
    int nodeLoc0  = warp * 32 + ngl * 8;   // local base of my 8 nodes

    float acc[8][4];
#pragma unroll
    for (int m = 0; m < 8; m++)
#pragma unroll
        for (int j = 0; j < 4; j++) acc[m][j] = 0.f;

    for (int c = 0; c < K / 32; c++) {
        // cooperative load of x chunk, transposed into smem
        int node = nodeBlock + tid;
        float4 tmp[8];
        if (node < NN) {
            const float4* xr = reinterpret_cast<const float4*>(src + (size_t)node * K + c * 32);
#pragma unroll
            for (int q = 0; q < 8; q++) tmp[q] = xr[q];
        } else {
#pragma unroll
            for (int q = 0; q < 8; q++) tmp[q] = make_float4(0.f, 0.f, 0.f, 0.f);
        }
#pragma unroll
        for (int q = 0; q < 8; q++) {
            xs[q * 4 + 0][tid] = tmp[q].x;
            xs[q * 4 + 1][tid] = tmp[q].y;
            xs[q * 4 + 2][tid] = tmp[q].z;
            xs[q * 4 + 3][tid] = tmp[q].w;
        }
        for (int i = tid; i < 1024; i += 256) ws[i >> 5][i & 31] = W[c * 1024 + i];
        __syncthreads();

#pragma unroll 8
        for (int kk = 0; kk < 32; kk++) {
            float4 wv = *reinterpret_cast<const float4*>(&ws[kk][k4 * 4]);
            float4 xa = *reinterpret_cast<const float4*>(&xs[kk][nodeLoc0]);
            float4 xb = *reinterpret_cast<const float4*>(&xs[kk][nodeLoc0 + 4]);
            float xv[8] = {xa.x, xa.y, xa.z, xa.w, xb.x, xb.y, xb.z, xb.w};
#pragma unroll
            for (int m = 0; m < 8; m++) {
                acc[m][0] += xv[m] * wv.x;
                acc[m][1] += xv[m] * wv.y;
                acc[m][2] += xv[m] * wv.z;
                acc[m][3] += xv[m] * wv.w;
            }
        }
        __syncthreads();
    }

    // epilogue: store h, and reduce es/ed across the 8 lanes sharing each node
    float4 asv = reinterpret_cast<const float4*>(a_s)[k4];
    float4 adv = reinterpret_cast<const float4*>(a_d)[k4];
#pragma unroll
    for (int m = 0; m < 8; m++) {
        int node = nodeBlock + nodeLoc0 + m;
        float sp = acc[m][0] * asv.x + acc[m][1] * asv.y + acc[m][2] * asv.z + acc[m][3] * asv.w;
        float dp = acc[m][0] * adv.x + acc[m][1] * adv.y + acc[m][2] * adv.z + acc[m][3] * adv.w;
#pragma unroll
        for (int off = 4; off > 0; off >>= 1) {
            sp += __shfl_xor_sync(0xffffffffu, sp, off);
            dp += __shfl_xor_sync(0xffffffffu, dp, off);
        }
        if (node < NN) {
            reinterpret_cast<float4*>(g_h + (size_t)node * 32)[k4] =
                make_float4(acc[m][0], acc[m][1], acc[m][2], acc[m][3]);
            if (k4 == 0) { g_es[node] = sp; g_ed[node] = dp; }
        }
    }
}

// ---------------- edge softmax + aggregation: one warp per dst node ----------------
__global__ void k_agg(const float* __restrict__ bias)
{
    int node = (blockIdx.x * blockDim.x + threadIdx.x) >> 5;
    int lane = threadIdx.x & 31;
    if (node >= NN) return;

    int deg = g_ctr[node];
    if (deg > CAP) deg = CAP;
    const int* row = g_csr + (size_t)node * CAP;
    float edi = g_ed[node];

    float acc = 0.f, den = 0.f;
    for (int base = 0; base < deg; base += 32) {
        int cnt = deg - base;
        if (cnt > 32) cnt = 32;
        int   s_l = 0;
        float e_l = 0.f;
        if (lane < cnt) {
            s_l = row[base + lane];
            e_l = g_es[s_l];
        }
        for (int e = 0; e < cnt; e++) {
            int   s  = __shfl_sync(0xffffffffu, s_l, e);
            float ee = __shfl_sync(0xffffffffu, e_l, e) + edi;
            ee = (ee > 0.f) ? ee : 0.2f * ee;
            float w = __expf(ee);
            den += w;
            acc += w * g_h[(size_t)s * 32 + lane];
        }
    }
    g_out[(size_t)node * 32 + lane] = acc / den + bias[lane];
}

// ---------------- global mean pool: batch is SORTED -> segmented reduction ----------
// one warp per graph; binary search for [start, end) of this graph's node range.
// d_out is written with plain stores only (no atomics anywhere near d_out).
__global__ void k_pool(const int* __restrict__ batch, float* __restrict__ out)
{
    int g    = (blockIdx.x * blockDim.x + threadIdx.x) >> 5;
    int lane = threadIdx.x & 31;
    if (g >= GG) return;

    // lower_bound(batch, g) and lower_bound(batch, g+1); uniform across the warp
    int lo = 0, hi = NN;
    while (lo < hi) { int mid = (lo + hi) >> 1; if (batch[mid] < g) lo = mid + 1; else hi = mid; }
    int start = lo;
    hi = NN;
    while (lo < hi) { int mid = (lo + hi) >> 1; if (batch[mid] < g + 1) lo = mid + 1; else hi = mid; }
    int end = lo;

    float acc = 0.f;
    for (int n = start; n < end; n++)
        acc += g_out[(size_t)n * 32 + lane];

    int cnt = end - start;
    out[(size_t)g * 32 + lane] = acc / (float)(cnt > 0 ? cnt : 1);
}

// ---------------- launch ----------------
extern "C" void kernel_launch(void* const* d_in, const int* in_sizes, int n_in,
                              void* d_out, int out_size)
{
    const float* x     = (const float*)d_in[0];
    const int*   ei    = (const int*)d_in[1];
    const int*   batch = (const int*)d_in[2];
    int E = in_sizes[1] / 2;

    const float *W[4], *as_[4], *ad_[4], *bs_[4];
    for (int l = 0; l < 4; l++) {
        W[l]   = (const float*)d_in[3 + 4 * l];
        as_[l] = (const float*)d_in[4 + 4 * l];
        ad_[l] = (const float*)d_in[5 + 4 * l];
        bs_[l] = (const float*)d_in[6 + 4 * l];
    }
    float* out = (float*)d_out;

    const int nodeBlocks = (NN + 255) / 256;          // 391
    const int warpBlocks = (NN * 32 + 255) / 256;     // 12500

    k_init<<<nodeBlocks, 256>>>();
    k_scatter<<<(E + 255) / 256, 256>>>(ei, ei + E, E);

    // layer 1 (K = 128, input = x)
    k_gemm<128, false><<<nodeBlocks, 256>>>(x, W[0], as_[0], ad_[0]);
    k_agg<<<warpBlocks, 256>>>(bs_[0]);

    // layers 2..4 (K = 32, input = g_out)
    for (int l = 1; l < 4; l++) {
        k_gemm<32, true><<<nodeBlocks, 256>>>(nullptr, W[l], as_[l], ad_[l]);
        k_agg<<<warpBlocks, 256>>>(bs_[l]);
    }

    k_pool<<<(GG * 32 + 255) / 256, 256>>>(batch, out);
}

// round 6
// speedup vs baseline: 1.3127x; 1.3127x over previous
#include <cuda_runtime.h>

#define NN 100000
#define GG 2048
#define CAP 64

// ---------------- device scratch (no allocations allowed) ----------------
__device__ int   g_ctr[NN];                 // per-dst edge counter (== degree after build)
__device__ int   g_csr[(size_t)NN * CAP];   // src ids per dst row (fixed stride)
__device__ float g_h  [(size_t)NN * 32];    // current layer h = xW
__device__ float g_out[(size_t)NN * 32];    // layer output / next layer input
__device__ float g_es [NN];
__device__ float g_ed [NN];

// ---------------- CSR build ----------------
__global__ void k_init()
{
    int i = blockIdx.x * blockDim.x + threadIdx.x;
    if (i < NN) {
        g_ctr[i] = 1;                // self loop occupies slot 0
        g_csr[(size_t)i * CAP] = i;
    }
}

__global__ void k_scatter(const int* __restrict__ src,
                          const int* __restrict__ dst, int E)
{
    int e = blockIdx.x * blockDim.x + threadIdx.x;
    if (e < E) {
        int d = dst[e];
        int s = src[e];
        if ((unsigned)d < NN && (unsigned)s < NN) {
            int pos = atomicAdd(&g_ctr[d], 1);
            if (pos < CAP) g_csr[(size_t)d * CAP + pos] = s;
        }
    }
}

// ---------------- GEMM: g_h[N,32] = X[N,K] @ W[K,32], fused es/ed ----------------
// block = 256 threads covers 256 nodes. Thread = 8 nodes x 4 out-cols.
// USE_GOUT selects layer input: false -> param X, true -> g_out (previous layer).
template <int K, bool USE_GOUT>
__global__ void k_gemm(const float* __restrict__ X, const float* __restrict__ W,
                       const float* __restrict__ a_s, const float* __restrict__ a_d)
{
    __shared__ float xs[32][260];   // transposed x chunk: xs[kk][node_local]
    __shared__ float ws[32][32];    // W chunk

    const float* __restrict__ src = USE_GOUT ? (const float*)g_out : X;

    int tid  = threadIdx.x;
    int lane = tid & 31;
    int warp = tid >> 5;
    int k4   = lane & 7;
    int ngl  = lane >> 3;
    int nodeBlock = blockIdx.x * 256;
    int nodeLoc0  = warp * 32 + ngl * 8;   // local base of my 8 nodes

    float acc[8][4];
#pragma unroll
    for (int m = 0; m < 8; m++)
#pragma unroll
        for (int j = 0; j < 4; j++) acc[m][j] = 0.f;

    for (int c = 0; c < K / 32; c++) {
        // cooperative load of x chunk, transposed into smem
        int node = nodeBlock + tid;
        float4 tmp[8];
        if (node < NN) {
            const float4* xr = reinterpret_cast<const float4*>(src + (size_t)node * K + c * 32);
#pragma unroll
            for (int q = 0; q < 8; q++) tmp[q] = xr[q];
        } else {
#pragma unroll
            for (int q = 0; q < 8; q++) tmp[q] = make_float4(0.f, 0.f, 0.f, 0.f);
        }
#pragma unroll
        for (int q = 0; q < 8; q++) {
            xs[q * 4 + 0][tid] = tmp[q].x;
            xs[q * 4 + 1][tid] = tmp[q].y;
            xs[q * 4 + 2][tid] = tmp[q].z;
            xs[q * 4 + 3][tid] = tmp[q].w;
        }
        for (int i = tid; i < 1024; i += 256) ws[i >> 5][i & 31] = W[c * 1024 + i];
        __syncthreads();

#pragma unroll 8
        for (int kk = 0; kk < 32; kk++) {
            float4 wv = *reinterpret_cast<const float4*>(&ws[kk][k4 * 4]);
            float4 xa = *reinterpret_cast<const float4*>(&xs[kk][nodeLoc0]);
            float4 xb = *reinterpret_cast<const float4*>(&xs[kk][nodeLoc0 + 4]);
            float xv[8] = {xa.x, xa.y, xa.z, xa.w, xb.x, xb.y, xb.z, xb.w};
#pragma unroll
            for (int m = 0; m < 8; m++) {
                acc[m][0] += xv[m] * wv.x;
                acc[m][1] += xv[m] * wv.y;
                acc[m][2] += xv[m] * wv.z;
                acc[m][3] += xv[m] * wv.w;
            }
        }
        __syncthreads();
    }

    // epilogue: store h, and reduce es/ed across the 8 lanes sharing each node
    float4 asv = reinterpret_cast<const float4*>(a_s)[k4];
    float4 adv = reinterpret_cast<const float4*>(a_d)[k4];
#pragma unroll
    for (int m = 0; m < 8; m++) {
        int node = nodeBlock + nodeLoc0 + m;
        float sp = acc[m][0] * asv.x + acc[m][1] * asv.y + acc[m][2] * asv.z + acc[m][3] * asv.w;
        float dp = acc[m][0] * adv.x + acc[m][1] * adv.y + acc[m][2] * adv.z + acc[m][3] * adv.w;
#pragma unroll
        for (int off = 4; off > 0; off >>= 1) {
            sp += __shfl_xor_sync(0xffffffffu, sp, off);
            dp += __shfl_xor_sync(0xffffffffu, dp, off);
        }
        if (node < NN) {
            reinterpret_cast<float4*>(g_h + (size_t)node * 32)[k4] =
                make_float4(acc[m][0], acc[m][1], acc[m][2], acc[m][3]);
            if (k4 == 0) { g_es[node] = sp; g_ed[node] = dp; }
        }
    }
}

// ---------------- edge softmax + aggregation ----------------
// 4 nodes per warp, 8 lanes per node (lane = g*8 + q), float4 of features per lane.
// Phase 1 (lane-parallel): weights for entries k*8+q, k=0..7; group-reduce denominator.
// Phase 2 (broadcast gather): one warp-instruction covers 4 edges (one per group).
__global__ void k_agg(const float* __restrict__ bias)
{
    const unsigned FULL = 0xffffffffu;
    int warpGlobal = (blockIdx.x * blockDim.x + threadIdx.x) >> 5;
    int lane = threadIdx.x & 31;
    int g = lane >> 3;          // node group within warp
    int q = lane & 7;           // feature quad within node

    int node = warpGlobal * 4 + g;
    bool valid = node < NN;

    int deg = 0;
    float edi = 0.f;
    if (valid) {
        deg = g_ctr[node];
        if (deg > CAP) deg = CAP;
        edi = g_ed[node];
    }
    const int* row = g_csr + (size_t)(valid ? node : 0) * CAP;

    // ---- phase 1: per-lane edge weights ----
    int   s_r[8];
    float w_r[8];
    float den = 0.f;
#pragma unroll
    for (int k = 0; k < 8; k++) {
        int e = k * 8 + q;
        int s = (e < deg) ? row[e] : 0;
        float w = 0.f;
        if (e < deg) {
            float ee = g_es[s] + edi;
            ee = (ee > 0.f) ? ee : 0.2f * ee;
            w = __expf(ee);
        }
        s_r[k] = s;
        w_r[k] = w;
        den += w;
    }
    // reduce den within the 8-lane group
#pragma unroll
    for (int off = 4; off > 0; off >>= 1)
        den += __shfl_xor_sync(FULL, den, off);

    // warp-max degree -> shared loop bound
    int degMax = deg;
#pragma unroll
    for (int off = 16; off > 0; off >>= 1) {
        int o = __shfl_xor_sync(FULL, degMax, off);
        degMax = o > degMax ? o : degMax;
    }

    // ---- phase 2: gather ----
    float4 acc = make_float4(0.f, 0.f, 0.f, 0.f);
    int base = g * 8;
#pragma unroll
    for (int k = 0; k < 8; k++) {
        if (k * 8 >= degMax) break;
#pragma unroll
        for (int j = 0; j < 8; j++) {
            int srcLane = base + j;
            int   s = __shfl_sync(FULL, s_r[k], srcLane);
            float w = __shfl_sync(FULL, w_r[k], srcLane);
            float4 hv = *reinterpret_cast<const float4*>(g_h + (size_t)s * 32 + q * 4);
            acc.x += w * hv.x;
            acc.y += w * hv.y;
            acc.z += w * hv.z;
            acc.w += w * hv.w;
        }
    }

    if (valid) {
        float inv = 1.f / den;
        float4 b4 = reinterpret_cast<const float4*>(bias)[q];
        float4 o;
        o.x = acc.x * inv + b4.x;
        o.y = acc.y * inv + b4.y;
        o.z = acc.z * inv + b4.z;
        o.w = acc.w * inv + b4.w;
        reinterpret_cast<float4*>(g_out + (size_t)node * 32)[q] = o;
    }
}

// ---------------- global mean pool: batch is SORTED -> segmented reduction ----------
// one warp per graph; binary search for [start, end) of this graph's node range.
__global__ void k_pool(const int* __restrict__ batch, float* __restrict__ out)
{
    int g    = (blockIdx.x * blockDim.x + threadIdx.x) >> 5;
    int lane = threadIdx.x & 31;
    if (g >= GG) return;

    int lo = 0, hi = NN;
    while (lo < hi) { int mid = (lo + hi) >> 1; if (batch[mid] < g) lo = mid + 1; else hi = mid; }
    int start = lo;
    hi = NN;
    while (lo < hi) { int mid = (lo + hi) >> 1; if (batch[mid] < g + 1) lo = mid + 1; else hi = mid; }
    int end = lo;

    float acc = 0.f;
    for (int n = start; n < end; n++)
        acc += g_out[(size_t)n * 32 + lane];

    int cnt = end - start;
    out[(size_t)g * 32 + lane] = acc / (float)(cnt > 0 ? cnt : 1);
}

// ---------------- launch ----------------
extern "C" void kernel_launch(void* const* d_in, const int* in_sizes, int n_in,
                              void* d_out, int out_size)
{
    const float* x     = (const float*)d_in[0];
    const int*   ei    = (const int*)d_in[1];
    const int*   batch = (const int*)d_in[2];
    int E = in_sizes[1] / 2;

    const float *W[4], *as_[4], *ad_[4], *bs_[4];
    for (int l = 0; l < 4; l++) {
        W[l]   = (const float*)d_in[3 + 4 * l];
        as_[l] = (const float*)d_in[4 + 4 * l];
        ad_[l] = (const float*)d_in[5 + 4 * l];
        bs_[l] = (const float*)d_in[6 + 4 * l];
    }
    float* out = (float*)d_out;

    const int nodeBlocks = (NN + 255) / 256;              // 391
    const int aggBlocks  = (NN + 4 * 8 - 1) / (4 * 8);    // 4 nodes/warp, 8 warps/block -> 3125

    k_init<<<nodeBlocks, 256>>>();
    k_scatter<<<(E + 255) / 256, 256>>>(ei, ei + E, E);

    // layer 1 (K = 128, input = x)
    k_gemm<128, false><<<nodeBlocks, 256>>>(x, W[0], as_[0], ad_[0]);
    k_agg<<<aggBlocks, 256>>>(bs_[0]);

    // layers 2..4 (K = 32, input = g_out)
    for (int l = 1; l < 4; l++) {
        k_gemm<32, true><<<nodeBlocks, 256>>>(nullptr, W[l], as_[l], ad_[l]);
        k_agg<<<aggBlocks, 256>>>(bs_[l]);
    }

    k_pool<<<(GG * 32 + 255) / 256, 256>>>(batch, out);
}